// round 2
// baseline (speedup 1.0000x reference)
#include <cuda_runtime.h>
#include <math.h>

#define PI_D 3.14159265358979323846

// ---------------- device scratch ----------------
__device__ float  g_wt[9*512*256];        // conv weights transposed [tap][c][o]
__device__ float  g_s2[256], g_b2[256];   // fused BN scale/shift for conv
__device__ float  g_conv[8*256*4096];     // conv output
__device__ float2 g_f[8*256*4096];        // fft2(conv)
__device__ float2 g_t[8*256*4096];        // complex scratch (attn out / gated f)
__device__ float  g_out2[8*512*4096];     // concat [out_f2; out_l2] (+x later)
__device__ float2 g_attnp[4*64*1024];     // attention logit partials (4 n-splits)
__device__ float2 g_attn[64*1024];        // softmaxed attention
__device__ float  g_invn[2048];           // inverse row norms
__device__ float2 g_D64f[4096];           // e^{-2pi i jk/64}
__device__ float2 g_D64i[4096];           // e^{+2pi i jk/64}
__device__ float2 g_tw[4096];             // e^{+2pi i n2 k1/4096}, idx n2*64+k1
__device__ float2 g_D32i[1024];           // e^{+2pi i jk/32} / 32

// ---------------- prep ----------------
__global__ void k_prep_w(const float* __restrict__ w) {
    int i = blockIdx.x*blockDim.x + threadIdx.x;
    if (i >= 9*512*256) return;
    int o = i % 256; int c = (i/256) % 512; int tap = i / (256*512);
    int ky = tap/3, kx = tap%3;
    g_wt[i] = w[((o*512 + c)*3 + ky)*3 + kx];
}

__global__ void k_prep_misc(const float* __restrict__ conv2_b, const float* __restrict__ g,
                            const float* __restrict__ bb, const float* __restrict__ m,
                            const float* __restrict__ v) {
    int i = blockIdx.x*blockDim.x + threadIdx.x;
    if (i < 4096) {
        int j = i >> 6, k = i & 63;
        double s, c;
        sincos(2.0*PI_D*(double)(j*k)/64.0, &s, &c);
        g_D64f[i] = make_float2((float)c, (float)(-s));
        g_D64i[i] = make_float2((float)c, (float)s);
        sincos(2.0*PI_D*(double)(j*k)/4096.0, &s, &c);
        g_tw[i] = make_float2((float)c, (float)s);
    }
    if (i < 1024) {
        int j = i >> 5, k = i & 31;
        double s, c;
        sincos(2.0*PI_D*(double)(j*k)/32.0, &s, &c);
        g_D32i[i] = make_float2((float)(c/32.0), (float)(s/32.0));
    }
    if (i < 256) {
        float sc = g[i] * rsqrtf(v[i] + 1e-5f);
        g_s2[i] = sc;
        g_b2[i] = (conv2_b[i] - m[i]) * sc + bb[i];
    }
    if (i < 4*64*1024) g_attnp[i] = make_float2(0.f, 0.f);
}

// ---------------- conv (dilated 3x3, 512->256) + BN + ReLU ----------------
#define CONV_CC 32
__global__ void k_conv(const float* __restrict__ x) {
    __shared__ float sIn[CONV_CC*3*22];
    int x0 = blockIdx.x*16, y = blockIdx.y, b = blockIdx.z;
    int o = threadIdx.x;
    float acc[16];
    #pragma unroll
    for (int s=0;s<16;s++) acc[s]=0.f;
    for (int c0=0;c0<512;c0+=CONV_CC) {
        __syncthreads();
        for (int e = threadIdx.x; e < 66*CONV_CC; e += 256) {
            int c = e % CONV_CC; int pos = e / CONV_CC;
            int ky = pos / 22, col = pos % 22;
            int yy = y + 3*ky - 3;
            int xx = x0 + col - 3;
            float v = 0.f;
            if (yy>=0 && yy<64 && xx>=0 && xx<64)
                v = x[((size_t)b*4096 + yy*64 + xx)*512 + c0 + c];
            sIn[(c*3 + ky)*22 + col] = v;
        }
        __syncthreads();
        for (int c=0;c<CONV_CC;c++) {
            #pragma unroll
            for (int ky=0;ky<3;ky++) {
                float rv[22];
                #pragma unroll
                for (int i=0;i<22;i++) rv[i] = sIn[(c*3+ky)*22 + i];
                #pragma unroll
                for (int kx=0;kx<3;kx++) {
                    float w = g_wt[((ky*3+kx)*512 + (c0+c))*256 + o];
                    #pragma unroll
                    for (int s=0;s<16;s++) acc[s] = fmaf(w, rv[s+3*kx], acc[s]);
                }
            }
        }
    }
    float sc = g_s2[o], sh = g_b2[o];
    size_t base = ((size_t)b*256 + o)*4096 + (size_t)y*64 + x0;
    #pragma unroll
    for (int s=0;s<16;s++) g_conv[base+s] = fmaxf(fmaf(acc[s], sc, sh), 0.f);
}

// ---------------- fft2 64x64 forward (real -> complex) ----------------
__global__ void k_fft2_fwd() {
    __shared__ float2 S[4096];
    int img = blockIdx.x;
    int t = threadIdx.x;
    const float* src = g_conv + (size_t)img*4096;
    for (int i=t;i<4096;i+=256) S[i] = make_float2(src[i], 0.f);
    __syncthreads();
    int k = t & 63, rg = t >> 6;
    float2 acc[16];
    // pass1: rows (over w): B[r][k] = sum_n A[r][n] * D[n][k]
    #pragma unroll
    for (int i=0;i<16;i++) acc[i]=make_float2(0.f,0.f);
    for (int n=0;n<64;n++) {
        float2 d = g_D64f[n*64+k];
        #pragma unroll
        for (int i=0;i<16;i++) {
            float2 a = S[(rg*16+i)*64 + n];
            acc[i].x = fmaf(a.x, d.x, fmaf(-a.y, d.y, acc[i].x));
            acc[i].y = fmaf(a.x, d.y, fmaf( a.y, d.x, acc[i].y));
        }
    }
    __syncthreads();
    #pragma unroll
    for (int i=0;i<16;i++) S[(rg*16+i)*64 + k] = acc[i];
    __syncthreads();
    // pass2: cols (over h): C[k1][k] = sum_r B[r][k] * D[r][k1]
    #pragma unroll
    for (int i=0;i<16;i++) acc[i]=make_float2(0.f,0.f);
    for (int r=0;r<64;r++) {
        float2 bv = S[r*64 + k];
        #pragma unroll
        for (int i=0;i<16;i++) {
            float2 d = g_D64f[r*64 + rg*16 + i];
            acc[i].x = fmaf(bv.x, d.x, fmaf(-bv.y, d.y, acc[i].x));
            acc[i].y = fmaf(bv.x, d.y, fmaf( bv.y, d.x, acc[i].y));
        }
    }
    float2* dst = g_f + (size_t)img*4096;
    #pragma unroll
    for (int i=0;i<16;i++) dst[(rg*16+i)*64 + k] = acc[i];
}

// ---------------- inverse row norms ----------------
__global__ void k_invnorm() {
    int row = blockIdx.x;
    const float2* p = g_f + (size_t)row*4096;
    float s = 0.f;
    for (int i=threadIdx.x;i<4096;i+=256) { float2 v = p[i]; s = fmaf(v.x,v.x,fmaf(v.y,v.y,s)); }
    __shared__ float red[256];
    red[threadIdx.x]=s; __syncthreads();
    for (int st=128;st>0;st>>=1){ if(threadIdx.x<st) red[threadIdx.x]+=red[threadIdx.x+st]; __syncthreads(); }
    if (threadIdx.x==0) g_invn[row] = 1.f / fmaxf(sqrtf(red[0]), 1e-12f);
}

// ---------------- attention logit partials (complex, no conjugate) ----------------
__global__ void k_attn() {
    __shared__ float2 F[32*65];
    int bh = blockIdx.x, p = blockIdx.y;
    int b = bh >> 3, hd = bh & 7;
    int t = threadIdx.x;
    int d = t & 31, cg = t >> 5;
    float2 acc[4];
    #pragma unroll
    for (int i=0;i<4;i++) acc[i]=make_float2(0.f,0.f);
    const float2* base = g_f + (((size_t)b*256 + hd*32)*4096);
    for (int n0 = p*1024; n0 < p*1024+1024; n0 += 64) {
        __syncthreads();
        for (int e=t; e<2048; e+=256) {
            int cc = e >> 6, j = e & 63;
            F[cc*65+j] = base[(size_t)cc*4096 + n0 + j];
        }
        __syncthreads();
        for (int j=0;j<64;j++) {
            float2 vd = F[d*65+j];
            #pragma unroll
            for (int i=0;i<4;i++) {
                float2 vc = F[(cg*4+i)*65 + j];
                acc[i].x = fmaf(vc.x,vd.x, fmaf(-vc.y,vd.y, acc[i].x));
                acc[i].y = fmaf(vc.x,vd.y, fmaf( vc.y,vd.x, acc[i].y));
            }
        }
    }
    float2* dst = g_attnp + ((size_t)p*64 + bh)*1024;
    #pragma unroll
    for (int i=0;i<4;i++) dst[(cg*4+i)*32 + d] = acc[i];
}

// ---------------- reduce partials + scale + softmax(re/im) ----------------
__global__ void k_softmax(const float* __restrict__ temperature) {
    int w = threadIdx.x >> 5, lane = threadIdx.x & 31;
    int row = blockIdx.x*8 + w;                // (b, hd, c)
    int b = row >> 8, ch = row & 255; int hd = ch >> 5, c = ch & 31;
    int bh = b*8+hd;
    size_t idx = (size_t)bh*1024 + c*32 + lane;
    float2 v = make_float2(0.f,0.f);
    for (int p=0;p<4;p++){ float2 q = g_attnp[(size_t)p*65536 + idx]; v.x+=q.x; v.y+=q.y; }
    float scale = g_invn[row] * g_invn[b*256 + hd*32 + lane] * temperature[hd];
    float re = v.x*scale, im = v.y*scale;
    float mre = re, mim = im;
    for (int s=16;s>0;s>>=1){ mre = fmaxf(mre, __shfl_xor_sync(0xffffffffu, mre, s));
                              mim = fmaxf(mim, __shfl_xor_sync(0xffffffffu, mim, s)); }
    float ere = expf(re-mre), eim = expf(im-mim);
    float sre=ere, sim=eim;
    for (int s=16;s>0;s>>=1){ sre += __shfl_xor_sync(0xffffffffu,sre,s);
                              sim += __shfl_xor_sync(0xffffffffu,sim,s); }
    g_attn[idx] = make_float2(ere/sre, eim/sim);
}

// ---------------- apply: out[c][n] = sum_d attn[c][d] * f[d][n] ----------------
__global__ void k_apply() {
    __shared__ float2 As[1024];
    int bh = blockIdx.x, nc = blockIdx.y;
    int b = bh>>3, hd = bh&7;
    int t = threadIdx.x;
    for (int e=t;e<1024;e+=256) As[e] = g_attn[(size_t)bh*1024 + e];
    __syncthreads();
    int n = nc*256 + t;
    const float2* fb = g_f + ((size_t)b*256 + hd*32)*4096 + n;
    float2 acc[32];
    #pragma unroll
    for (int c=0;c<32;c++) acc[c]=make_float2(0.f,0.f);
    for (int d=0;d<32;d++) {
        float2 v = fb[(size_t)d*4096];
        #pragma unroll
        for (int c=0;c<32;c++) {
            float2 a = As[c*32+d];
            acc[c].x = fmaf(a.x,v.x, fmaf(-a.y,v.y, acc[c].x));
            acc[c].y = fmaf(a.x,v.y, fmaf( a.y,v.x, acc[c].y));
        }
    }
    float2* ob = g_t + ((size_t)b*256 + hd*32)*4096 + n;
    #pragma unroll
    for (int c=0;c<32;c++) ob[(size_t)c*4096] = acc[c];
}

// ---------------- ifft over length-32 channel axis (in place, scaled 1/32) ----------------
__global__ void k_ifft32() {
    __shared__ float2 D[1024];
    int bh = blockIdx.x, nc = blockIdx.y;
    int t = threadIdx.x;
    for (int e=t;e<1024;e+=256) D[e] = g_D32i[e];
    __syncthreads();
    int b = bh>>3, hd = bh&7;
    int n = nc*256 + t;
    float2* col = g_t + ((size_t)b*256+hd*32)*4096 + n;
    float2 acc[32];
    #pragma unroll
    for (int k=0;k<32;k++) acc[k]=make_float2(0.f,0.f);
    for (int c=0;c<32;c++) {
        float2 v = col[(size_t)c*4096];
        #pragma unroll
        for (int k=0;k<32;k++) {
            float2 d = D[c*32+k];
            acc[k].x = fmaf(v.x,d.x, fmaf(-v.y,d.y,acc[k].x));
            acc[k].y = fmaf(v.x,d.y, fmaf( v.y,d.x,acc[k].y));
        }
    }
    #pragma unroll
    for (int k=0;k<32;k++) col[(size_t)k*4096] = acc[k];
}

// ---------------- ifft-4096 per row (four-step, D64), abs -> out2 lower half ----------------
__global__ void k_ifft4096() {
    __shared__ float2 S[4224];                  // 64*66 padded for final transpose
    int row = blockIdx.x;                       // b*256 + ch
    int t = threadIdx.x;
    const float2* src = g_t + (size_t)row*4096;
    for (int i=t;i<4096;i+=256) S[i]=src[i];
    __syncthreads();
    int k = t&63, rg = t>>6;
    float2 acc[16];
    // B1: FFT over n1 (stride 64). thread: n2=k, k1=rg*16+i
    #pragma unroll
    for(int i=0;i<16;i++)acc[i]=make_float2(0.f,0.f);
    for (int n1=0;n1<64;n1++){
        float2 a = S[n1*64 + k];
        #pragma unroll
        for (int i=0;i<16;i++){
            float2 d = g_D64i[n1*64 + rg*16+i];
            acc[i].x = fmaf(a.x,d.x,fmaf(-a.y,d.y,acc[i].x));
            acc[i].y = fmaf(a.x,d.y,fmaf( a.y,d.x,acc[i].y));
        }
    }
    __syncthreads();
    // twiddle + store B[k1][n2]
    #pragma unroll
    for (int i=0;i<16;i++){
        int k1 = rg*16+i;
        float2 tw = g_tw[k*64 + k1];
        float2 v; v.x = acc[i].x*tw.x - acc[i].y*tw.y; v.y = acc[i].x*tw.y + acc[i].y*tw.x;
        S[k1*64 + k] = v;
    }
    __syncthreads();
    // B3: FFT over n2. thread: k2=k, k1=rg*16+i
    #pragma unroll
    for(int i=0;i<16;i++)acc[i]=make_float2(0.f,0.f);
    for (int n2=0;n2<64;n2++){
        float2 d = g_D64i[n2*64 + k];
        #pragma unroll
        for (int i=0;i<16;i++){
            float2 bv = S[(rg*16+i)*64 + n2];
            acc[i].x = fmaf(bv.x,d.x,fmaf(-bv.y,d.y,acc[i].x));
            acc[i].y = fmaf(bv.x,d.y,fmaf( bv.y,d.x,acc[i].y));
        }
    }
    __syncthreads();
    // store transposed so final write is coalesced: out idx m = k1 + 64*k2
    #pragma unroll
    for (int i=0;i<16;i++) S[k*66 + rg*16+i] = acc[i];
    __syncthreads();
    int b = row >> 8, ch = row & 255;
    float* dst = g_out2 + ((size_t)b*512 + ch)*4096;
    const float inv = 1.f/4096.f;
    for (int i=t;i<4096;i+=256){ float2 v=S[(i>>6)*66 + (i&63)]; dst[i] = sqrtf(v.x*v.x+v.y*v.y)*inv; }
}

// ---------------- gating MLP + gate*f -> g_t ----------------
__global__ void k_gate(const float* __restrict__ w1_w, const float* __restrict__ w1_b,
                       const float* __restrict__ bnw_g, const float* __restrict__ bnw_b,
                       const float* __restrict__ bnw_m, const float* __restrict__ bnw_v,
                       const float* __restrict__ w2_w, const float* __restrict__ w2_b) {
    __shared__ float w1s[16*256];
    __shared__ float w2s[256*16];
    __shared__ float aw[16], dw[16], b2s[256];
    int b = blockIdx.x, nc = blockIdx.y;
    int t = threadIdx.x;
    for (int e=t;e<4096;e+=256){ w1s[e]=w1_w[e]; w2s[e]=w2_w[e]; }
    if (t<16){ float a = bnw_g[t]*rsqrtf(bnw_v[t]+1e-5f); aw[t]=a; dw[t]=(w1_b[t]-bnw_m[t])*a + bnw_b[t]; }
    b2s[t]=w2_b[t];
    __syncthreads();
    int n = nc*256 + t;
    const float2* fb = g_f + (size_t)b*256*4096 + n;
    float g1[16];
    #pragma unroll
    for (int j=0;j<16;j++) g1[j]=0.f;
    for (int c=0;c<256;c++){
        float v = fb[(size_t)c*4096].x;
        #pragma unroll
        for (int j=0;j<16;j++) g1[j] = fmaf(w1s[j*256+c], v, g1[j]);
    }
    #pragma unroll
    for (int j=0;j<16;j++) g1[j] = fmaxf(fmaf(g1[j], aw[j], dw[j]), 0.f);
    float2* ob = g_t + (size_t)b*256*4096 + n;
    for (int c=0;c<256;c++){
        float s = b2s[c];
        #pragma unroll
        for (int j=0;j<16;j++) s = fmaf(w2s[c*16+j], g1[j], s);
        float gt = 1.f/(1.f + expf(-s));
        float2 fv = fb[(size_t)c*4096];
        ob[(size_t)c*4096] = make_float2(fv.x*gt, fv.y*gt);
    }
}

// ---------------- ifft2 64x64 of gate*f, abs -> out2 upper half ----------------
__global__ void k_ifft2_gate() {
    __shared__ float2 S[4096];
    int img = blockIdx.x;
    int t = threadIdx.x;
    const float2* src = g_t + (size_t)img*4096;
    for (int i=t;i<4096;i+=256) S[i]=src[i];
    __syncthreads();
    int k=t&63, rg=t>>6;
    float2 acc[16];
    #pragma unroll
    for(int i=0;i<16;i++)acc[i]=make_float2(0.f,0.f);
    for (int n=0;n<64;n++){
        float2 d = g_D64i[n*64+k];
        #pragma unroll
        for (int i=0;i<16;i++){
            float2 a = S[(rg*16+i)*64+n];
            acc[i].x = fmaf(a.x,d.x,fmaf(-a.y,d.y,acc[i].x));
            acc[i].y = fmaf(a.x,d.y,fmaf( a.y,d.x,acc[i].y));
        }
    }
    __syncthreads();
    #pragma unroll
    for (int i=0;i<16;i++) S[(rg*16+i)*64+k]=acc[i];
    __syncthreads();
    #pragma unroll
    for(int i=0;i<16;i++)acc[i]=make_float2(0.f,0.f);
    for (int r=0;r<64;r++){
        float2 bv = S[r*64+k];
        #pragma unroll
        for (int i=0;i<16;i++){
            float2 d = g_D64i[r*64+rg*16+i];
            acc[i].x = fmaf(bv.x,d.x,fmaf(-bv.y,d.y,acc[i].x));
            acc[i].y = fmaf(bv.x,d.y,fmaf( bv.y,d.x,acc[i].y));
        }
    }
    int b = img>>8, ch = img&255;
    float* dst = g_out2 + ((size_t)b*512 + 256 + ch)*4096;
    const float inv = 1.f/4096.f;
    #pragma unroll
    for (int i=0;i<16;i++){
        float2 v = acc[i];
        dst[(rg*16+i)*64 + k] = sqrtf(v.x*v.x+v.y*v.y)*inv;
    }
}

// ---------------- residual add (transpose via smem) ----------------
__global__ void k_addx(const float* __restrict__ x) {
    __shared__ float s[32][33];
    int b = blockIdx.z;
    int ch0 = blockIdx.y*32;
    int n0 = blockIdx.x*32;
    int tj = threadIdx.x & 31;
    int ti = threadIdx.x >> 5;
    for (int i=ti;i<32;i+=8)
        s[i][tj] = x[((size_t)b*4096 + n0+i)*512 + ch0 + tj];
    __syncthreads();
    for (int j=ti;j<32;j+=8) {
        size_t idx = ((size_t)b*512 + ch0 + j)*4096 + n0 + tj;
        g_out2[idx] += s[tj][j];
    }
}

// ---------------- projection GEMM: out[b][n][o] = sum_ch pw[o][ch]*out2[b][ch][n]+pb ----------------
__global__ void k_proj(const float* __restrict__ pw, const float* __restrict__ pb,
                       float* __restrict__ out) {
    __shared__ float As[16][65];
    __shared__ float Bs[16][65];
    int b = blockIdx.z;
    int n0 = blockIdx.x*64;
    int o0 = blockIdx.y*64;
    int t = threadIdx.x;
    int tn = (t & 15)*4;
    int to = (t >> 4)*4;
    float acc[4][4];
    #pragma unroll
    for (int i=0;i<4;i++)
        #pragma unroll
        for (int j=0;j<4;j++) acc[i][j]=0.f;
    for (int k0=0;k0<512;k0+=16){
        __syncthreads();
        for (int e=t;e<1024;e+=256){
            int kk=e>>6, nn=e&63;
            As[kk][nn] = g_out2[((size_t)b*512 + k0+kk)*4096 + n0+nn];
        }
        for (int e=t;e<1024;e+=256){
            int oo=e>>4, kk=e&15;
            Bs[kk][oo] = pw[(size_t)(o0+oo)*512 + k0+kk];
        }
        __syncthreads();
        #pragma unroll
        for (int kk=0;kk<16;kk++){
            float a[4], bb[4];
            #pragma unroll
            for (int i=0;i<4;i++){ a[i]=As[kk][tn+i]; bb[i]=Bs[kk][to+i]; }
            #pragma unroll
            for (int j=0;j<4;j++)
                #pragma unroll
                for (int i=0;i<4;i++) acc[j][i] = fmaf(a[i], bb[j], acc[j][i]);
        }
    }
    #pragma unroll
    for (int i=0;i<4;i++){
        #pragma unroll
        for (int j=0;j<4;j++){
            size_t idx = ((size_t)b*4096 + n0+tn+i)*512 + o0+to+j;
            out[idx] = acc[j][i] + pb[o0+to+j];
        }
    }
}

// ---------------- launch ----------------
extern "C" void kernel_launch(void* const* d_in, const int* in_sizes, int n_in,
                              void* d_out, int out_size) {
    const float* x        = (const float*)d_in[0];
    const float* conv2_w  = (const float*)d_in[1];
    const float* conv2_b  = (const float*)d_in[2];
    const float* bn2_g    = (const float*)d_in[3];
    const float* bn2_b    = (const float*)d_in[4];
    const float* bn2_m    = (const float*)d_in[5];
    const float* bn2_v    = (const float*)d_in[6];
    const float* temp     = (const float*)d_in[7];
    const float* w1_w     = (const float*)d_in[8];
    const float* w1_b     = (const float*)d_in[9];
    const float* bnw_g    = (const float*)d_in[10];
    const float* bnw_b    = (const float*)d_in[11];
    const float* bnw_m    = (const float*)d_in[12];
    const float* bnw_v    = (const float*)d_in[13];
    const float* w2_w     = (const float*)d_in[14];
    const float* w2_b     = (const float*)d_in[15];
    const float* proj_w   = (const float*)d_in[16];
    const float* proj_b   = (const float*)d_in[17];
    float* out = (float*)d_out;

    k_prep_w<<<4608,256>>>(conv2_w);
    k_prep_misc<<<1024,256>>>(conv2_b, bn2_g, bn2_b, bn2_m, bn2_v);
    k_conv<<<dim3(4,64,8),256>>>(x);
    k_fft2_fwd<<<2048,256>>>();
    k_invnorm<<<2048,256>>>();
    k_attn<<<dim3(64,4),256>>>();
    k_softmax<<<256,256>>>(temp);
    k_apply<<<dim3(64,16),256>>>();
    k_ifft32<<<dim3(64,16),256>>>();
    k_ifft4096<<<2048,256>>>();
    k_gate<<<dim3(8,16),256>>>(w1_w,w1_b,bnw_g,bnw_b,bnw_m,bnw_v,w2_w,w2_b);
    k_ifft2_gate<<<2048,256>>>();
    k_addx<<<dim3(128,16,8),256>>>(x);
    k_proj<<<dim3(64,8,8),256>>>(proj_w, proj_b, out);
}

// round 4
// speedup vs baseline: 1.3592x; 1.3592x over previous
#include <cuda_runtime.h>
#include <cuda_bf16.h>
#include <math.h>
#include <stdint.h>

#define PI_D 3.14159265358979323846

__device__ __forceinline__ uint32_t smem_u32(const void* p) {
    uint32_t a;
    asm("{ .reg .u64 t; cvta.to.shared.u64 t, %1; cvt.u32.u64 %0, t; }" : "=r"(a) : "l"(p));
    return a;
}
static __device__ __forceinline__ uint32_t swz128(uint32_t off) { return off ^ ((off >> 3) & 0x70); }

__device__ __forceinline__ void cp_async16(uint32_t saddr, const void* gaddr, int sz) {
    asm volatile("cp.async.cg.shared.global [%0], [%1], 16, %2;"
                 :: "r"(saddr), "l"(gaddr), "r"(sz) : "memory");
}
__device__ __forceinline__ uint32_t lds32(uint32_t a) {
    uint32_t v; asm volatile("ld.shared.b32 %0, [%1];" : "=r"(v) : "r"(a)); return v;
}
__device__ __forceinline__ void mma16816(float* c, const uint32_t* a, uint32_t b0, uint32_t b1) {
    asm volatile("mma.sync.aligned.m16n8k16.row.col.f32.bf16.bf16.f32 "
        "{%0,%1,%2,%3}, {%4,%5,%6,%7}, {%8,%9}, {%0,%1,%2,%3};"
        : "+f"(c[0]), "+f"(c[1]), "+f"(c[2]), "+f"(c[3])
        : "r"(a[0]), "r"(a[1]), "r"(a[2]), "r"(a[3]), "r"(b0), "r"(b1));
}

// ---------------- device scratch ----------------
__device__ float  g_s2[256], g_b2[256];   // fused BN scale/shift for conv
__device__ float  g_conv[8*256*4096];     // conv output
__device__ float2 g_f[8*256*4096];        // fft2(conv)
__device__ float2 g_t[8*256*4096];        // complex scratch (attn out / gated f)
__device__ float  g_out2[8*512*4096];     // concat [out_f2; out_l2] (+x later)
__device__ float2 g_attnp[4*64*1024];     // attention logit partials (4 n-splits)
__device__ float2 g_attn[64*1024];        // softmaxed attention
__device__ float  g_invn[2048];           // inverse row norms
__device__ float2 g_D64f[4096];           // e^{-2pi i jk/64}
__device__ float2 g_D64i[4096];           // e^{+2pi i jk/64}
__device__ float2 g_tw[4096];             // e^{+2pi i n2 k1/4096}, idx n2*64+k1
__device__ float2 g_D32i[1024];           // e^{+2pi i jk/32} / 32
__device__ __nv_bfloat16 g_xhi[8*4096*512];
__device__ __nv_bfloat16 g_xlo[8*4096*512];
__device__ __nv_bfloat16 g_whi[9*256*512];  // [tap][o][c]
__device__ __nv_bfloat16 g_wlo[9*256*512];

// ---------------- prep ----------------
__global__ void k_split_x(const float* __restrict__ x) {
    size_t i = (size_t)blockIdx.x * 256 + threadIdx.x;
    if (i >= (size_t)8*4096*512) return;
    float v = x[i];
    __nv_bfloat16 h = __float2bfloat16(v);
    g_xhi[i] = h;
    g_xlo[i] = __float2bfloat16(v - __bfloat162float(h));
}

__global__ void k_split_w(const float* __restrict__ w) {
    int i = blockIdx.x * 256 + threadIdx.x;
    if (i >= 9*256*512) return;
    int c = i & 511, o = (i >> 9) & 255, tap = i >> 17;
    float v = w[(o*512 + c)*9 + tap];
    __nv_bfloat16 h = __float2bfloat16(v);
    g_whi[i] = h;
    g_wlo[i] = __float2bfloat16(v - __bfloat162float(h));
}

__global__ void k_prep_misc(const float* __restrict__ conv2_b, const float* __restrict__ g,
                            const float* __restrict__ bb, const float* __restrict__ m,
                            const float* __restrict__ v) {
    int i = blockIdx.x*blockDim.x + threadIdx.x;
    if (i < 4096) {
        int j = i >> 6, k = i & 63;
        double s, c;
        sincos(2.0*PI_D*(double)(j*k)/64.0, &s, &c);
        g_D64f[i] = make_float2((float)c, (float)(-s));
        g_D64i[i] = make_float2((float)c, (float)s);
        sincos(2.0*PI_D*(double)(j*k)/4096.0, &s, &c);
        g_tw[i] = make_float2((float)c, (float)s);
    }
    if (i < 1024) {
        int j = i >> 5, k = i & 31;
        double s, c;
        sincos(2.0*PI_D*(double)(j*k)/32.0, &s, &c);
        g_D32i[i] = make_float2((float)(c/32.0), (float)(s/32.0));
    }
    if (i < 256) {
        float sc = g[i] * rsqrtf(v[i] + 1e-5f);
        g_s2[i] = sc;
        g_b2[i] = (conv2_b[i] - m[i]) * sc + bb[i];
    }
    if (i < 4*64*1024) g_attnp[i] = make_float2(0.f, 0.f);
}

// ---------------- conv via HMMA implicit GEMM (bf16 split precision) ----------------
// CTA: M=128 positions x N=256 out ch. 8 warps, each 64x64 (4 mfrag x 8 nfrag m16n8k16).
// K chunks of 64 ch: 3 passes x 9 taps x 8 = 216 chunks, 2-stage cp.async pipeline.
#define CH_BYTES 49152         // A 16KB + B 32KB per stage
#define CONV_SMEM (2*CH_BYTES)

__global__ void __launch_bounds__(256, 1) k_conv_hmma() {
    extern __shared__ char smem[];
    uint32_t sb = smem_u32(smem);
    int tid = threadIdx.x, wid = tid >> 5, lane = tid & 31;
    int b = blockIdx.x >> 5;
    int m0 = (blockIdx.x & 31) << 7;
    int wm = wid & 1, wn = wid >> 1;      // warp tile: m=wm*64, n=wn*64

    float c[4][8][4];
    #pragma unroll
    for (int i = 0; i < 4; i++)
        #pragma unroll
        for (int j = 0; j < 8; j++)
            #pragma unroll
            for (int r = 0; r < 4; r++) c[i][j][r] = 0.f;

    auto issue = [&](int chunk) {
        int pass = chunk / 72, rem = chunk % 72, tap = rem >> 3, c0 = (rem & 7) << 6;
        const __nv_bfloat16* xs = ((pass == 2) ? g_xlo : g_xhi) + (size_t)b*4096*512 + c0;
        const __nv_bfloat16* ws = ((pass == 1) ? g_wlo : g_whi) + (size_t)tap*256*512 + c0;
        int oy = (tap/3)*3 - 3, ox = (tap%3)*3 - 3;
        uint32_t bo = (uint32_t)(chunk & 1) * CH_BYTES;
        // A tile: 128 rows (positions) x 64 ch, 128B/row SW128
        #pragma unroll
        for (int i = 0; i < 4; i++) {
            int idx = tid + i*256;
            int r = idx >> 3, q = idx & 7;
            int n = m0 + r;
            int ysr = (n >> 6) + oy, xsr = (n & 63) + ox;
            bool ok = ((unsigned)ysr < 64u) && ((unsigned)xsr < 64u);
            const __nv_bfloat16* gp = ok ? (xs + (size_t)(ysr*64 + xsr)*512 + q*8) : xs;
            cp_async16(sb + bo + swz128((uint32_t)(r*128 + q*16)), gp, ok ? 16 : 0);
        }
        // B tile: 256 rows (out ch) x 64 ch
        #pragma unroll
        for (int i = 0; i < 8; i++) {
            int idx = tid + i*256;
            int o = idx >> 3, q = idx & 7;
            cp_async16(sb + bo + 16384u + swz128((uint32_t)(o*128 + q*16)),
                       ws + (size_t)o*512 + q*8, 16);
        }
        asm volatile("cp.async.commit_group;" ::: "memory");
    };

    issue(0);
    #pragma unroll 1
    for (int ch = 0; ch < 216; ch++) {
        if (ch + 1 < 216) {
            issue(ch + 1);
            asm volatile("cp.async.wait_group 1;" ::: "memory");
        } else {
            asm volatile("cp.async.wait_group 0;" ::: "memory");
        }
        __syncthreads();
        uint32_t aBase = sb + (uint32_t)(ch & 1) * CH_BYTES;
        uint32_t bBase = aBase + 16384u;
        #pragma unroll
        for (int k16 = 0; k16 < 4; k16++) {
            uint32_t kb4 = (uint32_t)(k16*32 + (lane & 3)*4);
            uint32_t a[4][4];
            #pragma unroll
            for (int mf = 0; mf < 4; mf++) {
                uint32_t row = (uint32_t)(wm*64 + mf*16 + (lane >> 2));
                a[mf][0] = lds32(aBase + swz128(row*128 + kb4));
                a[mf][1] = lds32(aBase + swz128((row + 8)*128 + kb4));
                a[mf][2] = lds32(aBase + swz128(row*128 + kb4 + 16));
                a[mf][3] = lds32(aBase + swz128((row + 8)*128 + kb4 + 16));
            }
            #pragma unroll
            for (int nf = 0; nf < 8; nf++) {
                uint32_t nrow = (uint32_t)(wn*64 + nf*8 + (lane >> 2));
                uint32_t b0 = lds32(bBase + swz128(nrow*128 + kb4));
                uint32_t b1 = lds32(bBase + swz128(nrow*128 + kb4 + 16));
                #pragma unroll
                for (int mf = 0; mf < 4; mf++)
                    mma16816(c[mf][nf], a[mf], b0, b1);
            }
        }
        __syncthreads();
    }

    // epilogue: BN + ReLU, write g_conv[b][o][n]
    #pragma unroll
    for (int nf = 0; nf < 8; nf++) {
        int o = wn*64 + nf*8 + (lane & 3)*2;
        float s0 = g_s2[o],   t0 = g_b2[o];
        float s1 = g_s2[o+1], t1 = g_b2[o+1];
        float* d0 = g_conv + ((size_t)b*256 + o)*4096;
        float* d1 = d0 + 4096;
        #pragma unroll
        for (int mf = 0; mf < 4; mf++) {
            int n = m0 + wm*64 + mf*16 + (lane >> 2);
            d0[n]   = fmaxf(fmaf(c[mf][nf][0], s0, t0), 0.f);
            d1[n]   = fmaxf(fmaf(c[mf][nf][1], s1, t1), 0.f);
            d0[n+8] = fmaxf(fmaf(c[mf][nf][2], s0, t0), 0.f);
            d1[n+8] = fmaxf(fmaf(c[mf][nf][3], s1, t1), 0.f);
        }
    }
}

// ---------------- fft2 64x64 forward (real -> complex) ----------------
__global__ void k_fft2_fwd() {
    __shared__ float2 S[4096];
    int img = blockIdx.x;
    int t = threadIdx.x;
    const float* src = g_conv + (size_t)img*4096;
    for (int i=t;i<4096;i+=256) S[i] = make_float2(src[i], 0.f);
    __syncthreads();
    int k = t & 63, rg = t >> 6;
    float2 acc[16];
    #pragma unroll
    for (int i=0;i<16;i++) acc[i]=make_float2(0.f,0.f);
    for (int n=0;n<64;n++) {
        float2 d = g_D64f[n*64+k];
        #pragma unroll
        for (int i=0;i<16;i++) {
            float2 a = S[(rg*16+i)*64 + n];
            acc[i].x = fmaf(a.x, d.x, fmaf(-a.y, d.y, acc[i].x));
            acc[i].y = fmaf(a.x, d.y, fmaf( a.y, d.x, acc[i].y));
        }
    }
    __syncthreads();
    #pragma unroll
    for (int i=0;i<16;i++) S[(rg*16+i)*64 + k] = acc[i];
    __syncthreads();
    #pragma unroll
    for (int i=0;i<16;i++) acc[i]=make_float2(0.f,0.f);
    for (int r=0;r<64;r++) {
        float2 bv = S[r*64 + k];
        #pragma unroll
        for (int i=0;i<16;i++) {
            float2 d = g_D64f[r*64 + rg*16 + i];
            acc[i].x = fmaf(bv.x, d.x, fmaf(-bv.y, d.y, acc[i].x));
            acc[i].y = fmaf(bv.x, d.y, fmaf( bv.y, d.x, acc[i].y));
        }
    }
    float2* dst = g_f + (size_t)img*4096;
    #pragma unroll
    for (int i=0;i<16;i++) dst[(rg*16+i)*64 + k] = acc[i];
}

// ---------------- inverse row norms ----------------
__global__ void k_invnorm() {
    int row = blockIdx.x;
    const float2* p = g_f + (size_t)row*4096;
    float s = 0.f;
    for (int i=threadIdx.x;i<4096;i+=256) { float2 v = p[i]; s = fmaf(v.x,v.x,fmaf(v.y,v.y,s)); }
    __shared__ float red[256];
    red[threadIdx.x]=s; __syncthreads();
    for (int st=128;st>0;st>>=1){ if(threadIdx.x<st) red[threadIdx.x]+=red[threadIdx.x+st]; __syncthreads(); }
    if (threadIdx.x==0) g_invn[row] = 1.f / fmaxf(sqrtf(red[0]), 1e-12f);
}

// ---------------- attention logit partials ----------------
__global__ void k_attn() {
    __shared__ float2 F[32*65];
    int bh = blockIdx.x, p = blockIdx.y;
    int b = bh >> 3, hd = bh & 7;
    int t = threadIdx.x;
    int d = t & 31, cg = t >> 5;
    float2 acc[4];
    #pragma unroll
    for (int i=0;i<4;i++) acc[i]=make_float2(0.f,0.f);
    const float2* base = g_f + (((size_t)b*256 + hd*32)*4096);
    for (int n0 = p*1024; n0 < p*1024+1024; n0 += 64) {
        __syncthreads();
        for (int e=t; e<2048; e+=256) {
            int cc = e >> 6, j = e & 63;
            F[cc*65+j] = base[(size_t)cc*4096 + n0 + j];
        }
        __syncthreads();
        for (int j=0;j<64;j++) {
            float2 vd = F[d*65+j];
            #pragma unroll
            for (int i=0;i<4;i++) {
                float2 vc = F[(cg*4+i)*65 + j];
                acc[i].x = fmaf(vc.x,vd.x, fmaf(-vc.y,vd.y, acc[i].x));
                acc[i].y = fmaf(vc.x,vd.y, fmaf( vc.y,vd.x, acc[i].y));
            }
        }
    }
    float2* dst = g_attnp + ((size_t)p*64 + bh)*1024;
    #pragma unroll
    for (int i=0;i<4;i++) dst[(cg*4+i)*32 + d] = acc[i];
}

// ---------------- reduce partials + scale + softmax(re/im) ----------------
__global__ void k_softmax(const float* __restrict__ temperature) {
    int w = threadIdx.x >> 5, lane = threadIdx.x & 31;
    int row = blockIdx.x*8 + w;
    int b = row >> 8, ch = row & 255; int hd = ch >> 5, c = ch & 31;
    int bh = b*8+hd;
    size_t idx = (size_t)bh*1024 + c*32 + lane;
    float2 v = make_float2(0.f,0.f);
    for (int p=0;p<4;p++){ float2 q = g_attnp[(size_t)p*65536 + idx]; v.x+=q.x; v.y+=q.y; }
    float scale = g_invn[row] * g_invn[b*256 + hd*32 + lane] * temperature[hd];
    float re = v.x*scale, im = v.y*scale;
    float mre = re, mim = im;
    for (int s=16;s>0;s>>=1){ mre = fmaxf(mre, __shfl_xor_sync(0xffffffffu, mre, s));
                              mim = fmaxf(mim, __shfl_xor_sync(0xffffffffu, mim, s)); }
    float ere = expf(re-mre), eim = expf(im-mim);
    float sre=ere, sim=eim;
    for (int s=16;s>0;s>>=1){ sre += __shfl_xor_sync(0xffffffffu,sre,s);
                              sim += __shfl_xor_sync(0xffffffffu,sim,s); }
    g_attn[idx] = make_float2(ere/sre, eim/sim);
}

// ---------------- apply attention ----------------
__global__ void k_apply() {
    __shared__ float2 As[1024];
    int bh = blockIdx.x, nc = blockIdx.y;
    int b = bh>>3, hd = bh&7;
    int t = threadIdx.x;
    for (int e=t;e<1024;e+=256) As[e] = g_attn[(size_t)bh*1024 + e];
    __syncthreads();
    int n = nc*256 + t;
    const float2* fb = g_f + ((size_t)b*256 + hd*32)*4096 + n;
    float2 acc[32];
    #pragma unroll
    for (int c=0;c<32;c++) acc[c]=make_float2(0.f,0.f);
    for (int d=0;d<32;d++) {
        float2 v = fb[(size_t)d*4096];
        #pragma unroll
        for (int c=0;c<32;c++) {
            float2 a = As[c*32+d];
            acc[c].x = fmaf(a.x,v.x, fmaf(-a.y,v.y, acc[c].x));
            acc[c].y = fmaf(a.x,v.y, fmaf( a.y,v.x, acc[c].y));
        }
    }
    float2* ob = g_t + ((size_t)b*256 + hd*32)*4096 + n;
    #pragma unroll
    for (int c=0;c<32;c++) ob[(size_t)c*4096] = acc[c];
}

// ---------------- ifft over length-32 channel axis ----------------
__global__ void k_ifft32() {
    __shared__ float2 D[1024];
    int bh = blockIdx.x, nc = blockIdx.y;
    int t = threadIdx.x;
    for (int e=t;e<1024;e+=256) D[e] = g_D32i[e];
    __syncthreads();
    int b = bh>>3, hd = bh&7;
    int n = nc*256 + t;
    float2* col = g_t + ((size_t)b*256+hd*32)*4096 + n;
    float2 acc[32];
    #pragma unroll
    for (int k=0;k<32;k++) acc[k]=make_float2(0.f,0.f);
    for (int c=0;c<32;c++) {
        float2 v = col[(size_t)c*4096];
        #pragma unroll
        for (int k=0;k<32;k++) {
            float2 d = D[c*32+k];
            acc[k].x = fmaf(v.x,d.x, fmaf(-v.y,d.y,acc[k].x));
            acc[k].y = fmaf(v.x,d.y, fmaf( v.y,d.x,acc[k].y));
        }
    }
    #pragma unroll
    for (int k=0;k<32;k++) col[(size_t)k*4096] = acc[k];
}

// ---------------- ifft-4096 per row ----------------
__global__ void k_ifft4096() {
    __shared__ float2 S[4224];
    int row = blockIdx.x;
    int t = threadIdx.x;
    const float2* src = g_t + (size_t)row*4096;
    for (int i=t;i<4096;i+=256) S[i]=src[i];
    __syncthreads();
    int k = t&63, rg = t>>6;
    float2 acc[16];
    #pragma unroll
    for(int i=0;i<16;i++)acc[i]=make_float2(0.f,0.f);
    for (int n1=0;n1<64;n1++){
        float2 a = S[n1*64 + k];
        #pragma unroll
        for (int i=0;i<16;i++){
            float2 d = g_D64i[n1*64 + rg*16+i];
            acc[i].x = fmaf(a.x,d.x,fmaf(-a.y,d.y,acc[i].x));
            acc[i].y = fmaf(a.x,d.y,fmaf( a.y,d.x,acc[i].y));
        }
    }
    __syncthreads();
    #pragma unroll
    for (int i=0;i<16;i++){
        int k1 = rg*16+i;
        float2 tw = g_tw[k*64 + k1];
        float2 v; v.x = acc[i].x*tw.x - acc[i].y*tw.y; v.y = acc[i].x*tw.y + acc[i].y*tw.x;
        S[k1*64 + k] = v;
    }
    __syncthreads();
    #pragma unroll
    for(int i=0;i<16;i++)acc[i]=make_float2(0.f,0.f);
    for (int n2=0;n2<64;n2++){
        float2 d = g_D64i[n2*64 + k];
        #pragma unroll
        for (int i=0;i<16;i++){
            float2 bv = S[(rg*16+i)*64 + n2];
            acc[i].x = fmaf(bv.x,d.x,fmaf(-bv.y,d.y,acc[i].x));
            acc[i].y = fmaf(bv.x,d.y,fmaf( bv.y,d.x,acc[i].y));
        }
    }
    __syncthreads();
    #pragma unroll
    for (int i=0;i<16;i++) S[k*66 + rg*16+i] = acc[i];
    __syncthreads();
    int b = row >> 8, ch = row & 255;
    float* dst = g_out2 + ((size_t)b*512 + ch)*4096;
    const float inv = 1.f/4096.f;
    for (int i=t;i<4096;i+=256){ float2 v=S[(i>>6)*66 + (i&63)]; dst[i] = sqrtf(v.x*v.x+v.y*v.y)*inv; }
}

// ---------------- gating MLP + gate*f -> g_t ----------------
__global__ void k_gate(const float* __restrict__ w1_w, const float* __restrict__ w1_b,
                       const float* __restrict__ bnw_g, const float* __restrict__ bnw_b,
                       const float* __restrict__ bnw_m, const float* __restrict__ bnw_v,
                       const float* __restrict__ w2_w, const float* __restrict__ w2_b) {
    __shared__ float w1s[16*256];
    __shared__ float w2s[256*16];
    __shared__ float aw[16], dw[16], b2s[256];
    int b = blockIdx.x, nc = blockIdx.y;
    int t = threadIdx.x;
    for (int e=t;e<4096;e+=256){ w1s[e]=w1_w[e]; w2s[e]=w2_w[e]; }
    if (t<16){ float a = bnw_g[t]*rsqrtf(bnw_v[t]+1e-5f); aw[t]=a; dw[t]=(w1_b[t]-bnw_m[t])*a + bnw_b[t]; }
    b2s[t]=w2_b[t];
    __syncthreads();
    int n = nc*256 + t;
    const float2* fb = g_f + (size_t)b*256*4096 + n;
    float g1[16];
    #pragma unroll
    for (int j=0;j<16;j++) g1[j]=0.f;
    for (int c=0;c<256;c++){
        float v = fb[(size_t)c*4096].x;
        #pragma unroll
        for (int j=0;j<16;j++) g1[j] = fmaf(w1s[j*256+c], v, g1[j]);
    }
    #pragma unroll
    for (int j=0;j<16;j++) g1[j] = fmaxf(fmaf(g1[j], aw[j], dw[j]), 0.f);
    float2* ob = g_t + (size_t)b*256*4096 + n;
    for (int c=0;c<256;c++){
        float s = b2s[c];
        #pragma unroll
        for (int j=0;j<16;j++) s = fmaf(w2s[c*16+j], g1[j], s);
        float gt = 1.f/(1.f + expf(-s));
        float2 fv = fb[(size_t)c*4096];
        ob[(size_t)c*4096] = make_float2(fv.x*gt, fv.y*gt);
    }
}

// ---------------- ifft2 64x64 of gate*f ----------------
__global__ void k_ifft2_gate() {
    __shared__ float2 S[4096];
    int img = blockIdx.x;
    int t = threadIdx.x;
    const float2* src = g_t + (size_t)img*4096;
    for (int i=t;i<4096;i+=256) S[i]=src[i];
    __syncthreads();
    int k=t&63, rg=t>>6;
    float2 acc[16];
    #pragma unroll
    for(int i=0;i<16;i++)acc[i]=make_float2(0.f,0.f);
    for (int n=0;n<64;n++){
        float2 d = g_D64i[n*64+k];
        #pragma unroll
        for (int i=0;i<16;i++){
            float2 a = S[(rg*16+i)*64+n];
            acc[i].x = fmaf(a.x,d.x,fmaf(-a.y,d.y,acc[i].x));
            acc[i].y = fmaf(a.x,d.y,fmaf( a.y,d.x,acc[i].y));
        }
    }
    __syncthreads();
    #pragma unroll
    for (int i=0;i<16;i++) S[(rg*16+i)*64+k]=acc[i];
    __syncthreads();
    #pragma unroll
    for(int i=0;i<16;i++)acc[i]=make_float2(0.f,0.f);
    for (int r=0;r<64;r++){
        float2 bv = S[r*64+k];
        #pragma unroll
        for (int i=0;i<16;i++){
            float2 d = g_D64i[r*64+rg*16+i];
            acc[i].x = fmaf(bv.x,d.x,fmaf(-bv.y,d.y,acc[i].x));
            acc[i].y = fmaf(bv.x,d.y,fmaf( bv.y,d.x,acc[i].y));
        }
    }
    int b = img>>8, ch = img&255;
    float* dst = g_out2 + ((size_t)b*512 + 256 + ch)*4096;
    const float inv = 1.f/4096.f;
    #pragma unroll
    for (int i=0;i<16;i++){
        float2 v = acc[i];
        dst[(rg*16+i)*64 + k] = sqrtf(v.x*v.x+v.y*v.y)*inv;
    }
}

// ---------------- residual add ----------------
__global__ void k_addx(const float* __restrict__ x) {
    __shared__ float s[32][33];
    int b = blockIdx.z;
    int ch0 = blockIdx.y*32;
    int n0 = blockIdx.x*32;
    int tj = threadIdx.x & 31;
    int ti = threadIdx.x >> 5;
    for (int i=ti;i<32;i+=8)
        s[i][tj] = x[((size_t)b*4096 + n0+i)*512 + ch0 + tj];
    __syncthreads();
    for (int j=ti;j<32;j+=8) {
        size_t idx = ((size_t)b*512 + ch0 + j)*4096 + n0 + tj;
        g_out2[idx] += s[tj][j];
    }
}

// ---------------- projection GEMM ----------------
__global__ void k_proj(const float* __restrict__ pw, const float* __restrict__ pb,
                       float* __restrict__ out) {
    __shared__ float As[16][65];
    __shared__ float Bs[16][65];
    int b = blockIdx.z;
    int n0 = blockIdx.x*64;
    int o0 = blockIdx.y*64;
    int t = threadIdx.x;
    int tn = (t & 15)*4;
    int to = (t >> 4)*4;
    float acc[4][4];
    #pragma unroll
    for (int i=0;i<4;i++)
        #pragma unroll
        for (int j=0;j<4;j++) acc[i][j]=0.f;
    for (int k0=0;k0<512;k0+=16){
        __syncthreads();
        for (int e=t;e<1024;e+=256){
            int kk=e>>6, nn=e&63;
            As[kk][nn] = g_out2[((size_t)b*512 + k0+kk)*4096 + n0+nn];
        }
        for (int e=t;e<1024;e+=256){
            int oo=e>>4, kk=e&15;
            Bs[kk][oo] = pw[(size_t)(o0+oo)*512 + k0+kk];
        }
        __syncthreads();
        #pragma unroll
        for (int kk=0;kk<16;kk++){
            float a[4], bb[4];
            #pragma unroll
            for (int i=0;i<4;i++){ a[i]=As[kk][tn+i]; bb[i]=Bs[kk][to+i]; }
            #pragma unroll
            for (int j=0;j<4;j++)
                #pragma unroll
                for (int i=0;i<4;i++) acc[j][i] = fmaf(a[i], bb[j], acc[j][i]);
        }
    }
    #pragma unroll
    for (int i=0;i<4;i++){
        #pragma unroll
        for (int j=0;j<4;j++){
            size_t idx = ((size_t)b*4096 + n0+tn+i)*512 + o0+to+j;
            out[idx] = acc[j][i] + pb[o0+to+j];
        }
    }
}

// ---------------- launch ----------------
extern "C" void kernel_launch(void* const* d_in, const int* in_sizes, int n_in,
                              void* d_out, int out_size) {
    const float* x        = (const float*)d_in[0];
    const float* conv2_w  = (const float*)d_in[1];
    const float* conv2_b  = (const float*)d_in[2];
    const float* bn2_g    = (const float*)d_in[3];
    const float* bn2_b    = (const float*)d_in[4];
    const float* bn2_m    = (const float*)d_in[5];
    const float* bn2_v    = (const float*)d_in[6];
    const float* temp     = (const float*)d_in[7];
    const float* w1_w     = (const float*)d_in[8];
    const float* w1_b     = (const float*)d_in[9];
    const float* bnw_g    = (const float*)d_in[10];
    const float* bnw_b    = (const float*)d_in[11];
    const float* bnw_m    = (const float*)d_in[12];
    const float* bnw_v    = (const float*)d_in[13];
    const float* w2_w     = (const float*)d_in[14];
    const float* w2_b     = (const float*)d_in[15];
    const float* proj_w   = (const float*)d_in[16];
    const float* proj_b   = (const float*)d_in[17];
    float* out = (float*)d_out;

    static bool attr_set = false;
    if (!attr_set) {
        cudaFuncSetAttribute(k_conv_hmma, cudaFuncAttributeMaxDynamicSharedMemorySize, CONV_SMEM);
        attr_set = true;
    }

    k_split_x<<<65536,256>>>(x);
    k_split_w<<<4608,256>>>(conv2_w);
    k_prep_misc<<<1024,256>>>(conv2_b, bn2_g, bn2_b, bn2_m, bn2_v);
    k_conv_hmma<<<256,256,CONV_SMEM>>>();
    k_fft2_fwd<<<2048,256>>>();
    k_invnorm<<<2048,256>>>();
    k_attn<<<dim3(64,4),256>>>();
    k_softmax<<<256,256>>>(temp);
    k_apply<<<dim3(64,16),256>>>();
    k_ifft32<<<dim3(64,16),256>>>();
    k_ifft4096<<<2048,256>>>();
    k_gate<<<dim3(8,16),256>>>(w1_w,w1_b,bnw_g,bnw_b,bnw_m,bnw_v,w2_w,w2_b);
    k_ifft2_gate<<<2048,256>>>();
    k_addx<<<dim3(128,16,8),256>>>(x);
    k_proj<<<dim3(64,8,8),256>>>(proj_w, proj_b, out);
}

// round 5
// speedup vs baseline: 1.8218x; 1.3404x over previous
#include <cuda_runtime.h>
#include <cuda_bf16.h>
#include <math.h>
#include <stdint.h>

#define PI_D 3.14159265358979323846

__device__ __forceinline__ uint32_t smem_u32(const void* p) {
    uint32_t a;
    asm("{ .reg .u64 t; cvta.to.shared.u64 t, %1; cvt.u32.u64 %0, t; }" : "=r"(a) : "l"(p));
    return a;
}
static __device__ __forceinline__ uint32_t swz128(uint32_t off) { return off ^ ((off >> 3) & 0x70); }

__device__ __forceinline__ void cp_async16(uint32_t saddr, const void* gaddr, int sz) {
    asm volatile("cp.async.cg.shared.global [%0], [%1], 16, %2;"
                 :: "r"(saddr), "l"(gaddr), "r"(sz) : "memory");
}
__device__ __forceinline__ void ldmx4(uint32_t* r, uint32_t addr) {
    asm volatile("ldmatrix.sync.aligned.m8n8.x4.shared.b16 {%0,%1,%2,%3}, [%4];"
        : "=r"(r[0]), "=r"(r[1]), "=r"(r[2]), "=r"(r[3]) : "r"(addr));
}
__device__ __forceinline__ void mma16816(float* c, const uint32_t* a, uint32_t b0, uint32_t b1) {
    asm volatile("mma.sync.aligned.m16n8k16.row.col.f32.bf16.bf16.f32 "
        "{%0,%1,%2,%3}, {%4,%5,%6,%7}, {%8,%9}, {%0,%1,%2,%3};"
        : "+f"(c[0]), "+f"(c[1]), "+f"(c[2]), "+f"(c[3])
        : "r"(a[0]), "r"(a[1]), "r"(a[2]), "r"(a[3]), "r"(b0), "r"(b1));
}

// ---------------- device scratch ----------------
__device__ float  g_s2[256], g_b2[256];
__device__ float  g_conv[8*256*4096];
__device__ float2 g_f[8*256*4096];
__device__ float2 g_t[8*256*4096];
__device__ float  g_out2[8*512*4096];     // concat [out_f2; out_l2] (pre-residual)
__device__ float2 g_attnp[4*64*1024];
__device__ float2 g_attn[64*1024];
__device__ float  g_invn[2048];
__device__ float2 g_D64f[4096];
__device__ float2 g_D64i[4096];
__device__ float2 g_tw[4096];
__device__ float2 g_D32i[1024];
__device__ __nv_bfloat16 g_xhi[8*4096*512];
__device__ __nv_bfloat16 g_xlo[8*4096*512];
__device__ __nv_bfloat16 g_whi[9*256*512];  // [tap][o][c]
__device__ __nv_bfloat16 g_wlo[9*256*512];
__device__ __nv_bfloat16 g_o2hi[8*4096*512];  // (out2 + x) in [b][n][ch] bf16
__device__ __nv_bfloat16 g_o2lo[8*4096*512];
__device__ __nv_bfloat16 g_pwhi[512*512];     // proj_w [o][ch]
__device__ __nv_bfloat16 g_pwlo[512*512];

// ---------------- prep ----------------
__global__ void k_split_x(const float* __restrict__ x) {
    size_t i = (size_t)blockIdx.x * 256 + threadIdx.x;
    if (i >= (size_t)8*4096*512) return;
    float v = x[i];
    __nv_bfloat16 h = __float2bfloat16(v);
    g_xhi[i] = h;
    g_xlo[i] = __float2bfloat16(v - __bfloat162float(h));
}

__global__ void k_split_w(const float* __restrict__ w) {
    int i = blockIdx.x * 256 + threadIdx.x;
    if (i >= 9*256*512) return;
    int c = i & 511, o = (i >> 9) & 255, tap = i >> 17;
    float v = w[(o*512 + c)*9 + tap];
    __nv_bfloat16 h = __float2bfloat16(v);
    g_whi[i] = h;
    g_wlo[i] = __float2bfloat16(v - __bfloat162float(h));
}

__global__ void k_split_pw(const float* __restrict__ pw) {
    int i = blockIdx.x * 256 + threadIdx.x;
    if (i >= 512*512) return;
    float v = pw[i];
    __nv_bfloat16 h = __float2bfloat16(v);
    g_pwhi[i] = h;
    g_pwlo[i] = __float2bfloat16(v - __bfloat162float(h));
}

__global__ void k_prep_misc(const float* __restrict__ conv2_b, const float* __restrict__ g,
                            const float* __restrict__ bb, const float* __restrict__ m,
                            const float* __restrict__ v) {
    int i = blockIdx.x*blockDim.x + threadIdx.x;
    if (i < 4096) {
        int j = i >> 6, k = i & 63;
        double s, c;
        sincos(2.0*PI_D*(double)(j*k)/64.0, &s, &c);
        g_D64f[i] = make_float2((float)c, (float)(-s));
        g_D64i[i] = make_float2((float)c, (float)s);
        sincos(2.0*PI_D*(double)(j*k)/4096.0, &s, &c);
        g_tw[i] = make_float2((float)c, (float)s);
    }
    if (i < 1024) {
        int j = i >> 5, k = i & 31;
        double s, c;
        sincos(2.0*PI_D*(double)(j*k)/32.0, &s, &c);
        g_D32i[i] = make_float2((float)(c/32.0), (float)(s/32.0));
    }
    if (i < 256) {
        float sc = g[i] * rsqrtf(v[i] + 1e-5f);
        g_s2[i] = sc;
        g_b2[i] = (conv2_b[i] - m[i]) * sc + bb[i];
    }
    if (i < 4*64*1024) g_attnp[i] = make_float2(0.f, 0.f);
}

// ---------------- conv via HMMA implicit GEMM (bf16 split, ldmatrix, 3-stage) ----------------
#define CH_BYTES 49152
#define CONV_STAGES 3
#define CONV_SMEM (CONV_STAGES*CH_BYTES)

__global__ void __launch_bounds__(256, 1) k_conv_hmma() {
    extern __shared__ char smem[];
    uint32_t sb = smem_u32(smem);
    int tid = threadIdx.x, wid = tid >> 5, lane = tid & 31;
    int b = blockIdx.x >> 5;
    int m0 = (blockIdx.x & 31) << 7;
    int wm = wid & 1, wn = wid >> 1;

    float c[4][8][4];
    #pragma unroll
    for (int i = 0; i < 4; i++)
        #pragma unroll
        for (int j = 0; j < 8; j++)
            #pragma unroll
            for (int r = 0; r < 4; r++) c[i][j][r] = 0.f;

    auto issue = [&](int chunk) {
        int pass = chunk / 72, rem = chunk % 72, tap = rem >> 3, c0 = (rem & 7) << 6;
        const __nv_bfloat16* xs = ((pass == 2) ? g_xlo : g_xhi) + (size_t)b*4096*512 + c0;
        const __nv_bfloat16* ws = ((pass == 1) ? g_wlo : g_whi) + (size_t)tap*256*512 + c0;
        int oy = (tap/3)*3 - 3, ox = (tap%3)*3 - 3;
        uint32_t bo = (uint32_t)(chunk % CONV_STAGES) * CH_BYTES;
        #pragma unroll
        for (int i = 0; i < 4; i++) {
            int idx = tid + i*256;
            int r = idx >> 3, q = idx & 7;
            int n = m0 + r;
            int ysr = (n >> 6) + oy, xsr = (n & 63) + ox;
            bool ok = ((unsigned)ysr < 64u) && ((unsigned)xsr < 64u);
            const __nv_bfloat16* gp = ok ? (xs + (size_t)(ysr*64 + xsr)*512 + q*8) : xs;
            cp_async16(sb + bo + swz128((uint32_t)(r*128 + q*16)), gp, ok ? 16 : 0);
        }
        #pragma unroll
        for (int i = 0; i < 8; i++) {
            int idx = tid + i*256;
            int o = idx >> 3, q = idx & 7;
            cp_async16(sb + bo + 16384u + swz128((uint32_t)(o*128 + q*16)),
                       ws + (size_t)o*512 + q*8, 16);
        }
        asm volatile("cp.async.commit_group;" ::: "memory");
    };

    issue(0); issue(1);
    int sub = lane >> 3, lr = lane & 7;
    #pragma unroll 1
    for (int ch = 0; ch < 216; ch++) {
        if (ch + 2 < 216) {
            issue(ch + 2);
            asm volatile("cp.async.wait_group 2;" ::: "memory");
        } else {
            asm volatile("cp.async.wait_group 0;" ::: "memory");
        }
        __syncthreads();
        uint32_t aBase = sb + (uint32_t)(ch % CONV_STAGES) * CH_BYTES;
        uint32_t bBase = aBase + 16384u;
        #pragma unroll
        for (int k16 = 0; k16 < 4; k16++) {
            uint32_t kb = (uint32_t)(k16*32);
            uint32_t a[4][4];
            #pragma unroll
            for (int mf = 0; mf < 4; mf++) {
                uint32_t row = (uint32_t)(wm*64 + mf*16 + ((sub & 1) << 3) + lr);
                uint32_t col = kb + ((uint32_t)(sub >> 1) << 4);
                ldmx4(a[mf], aBase + swz128(row*128 + col));
            }
            #pragma unroll
            for (int nfp = 0; nfp < 4; nfp++) {
                uint32_t brow = (uint32_t)(wn*64 + nfp*16 + ((sub & 2) << 2) + lr);
                uint32_t bcol = kb + ((uint32_t)(sub & 1) << 4);
                uint32_t bf[4];
                ldmx4(bf, bBase + swz128(brow*128 + bcol));
                #pragma unroll
                for (int mf = 0; mf < 4; mf++) {
                    mma16816(c[mf][nfp*2],     a[mf], bf[0], bf[1]);
                    mma16816(c[mf][nfp*2 + 1], a[mf], bf[2], bf[3]);
                }
            }
        }
        __syncthreads();
    }

    #pragma unroll
    for (int nf = 0; nf < 8; nf++) {
        int o = wn*64 + nf*8 + (lane & 3)*2;
        float s0 = g_s2[o],   t0 = g_b2[o];
        float s1 = g_s2[o+1], t1 = g_b2[o+1];
        float* d0 = g_conv + ((size_t)b*256 + o)*4096;
        float* d1 = d0 + 4096;
        #pragma unroll
        for (int mf = 0; mf < 4; mf++) {
            int n = m0 + wm*64 + mf*16 + (lane >> 2);
            d0[n]   = fmaxf(fmaf(c[mf][nf][0], s0, t0), 0.f);
            d1[n]   = fmaxf(fmaf(c[mf][nf][1], s1, t1), 0.f);
            d0[n+8] = fmaxf(fmaf(c[mf][nf][2], s0, t0), 0.f);
            d1[n+8] = fmaxf(fmaf(c[mf][nf][3], s1, t1), 0.f);
        }
    }
}

// ---------------- fft2 64x64 forward (real -> complex) ----------------
__global__ void k_fft2_fwd() {
    __shared__ float2 S[4096];
    int img = blockIdx.x;
    int t = threadIdx.x;
    const float* src = g_conv + (size_t)img*4096;
    for (int i=t;i<4096;i+=256) S[i] = make_float2(src[i], 0.f);
    __syncthreads();
    int k = t & 63, rg = t >> 6;
    float2 acc[16];
    #pragma unroll
    for (int i=0;i<16;i++) acc[i]=make_float2(0.f,0.f);
    for (int n=0;n<64;n++) {
        float2 d = g_D64f[n*64+k];
        #pragma unroll
        for (int i=0;i<16;i++) {
            float2 a = S[(rg*16+i)*64 + n];
            acc[i].x = fmaf(a.x, d.x, fmaf(-a.y, d.y, acc[i].x));
            acc[i].y = fmaf(a.x, d.y, fmaf( a.y, d.x, acc[i].y));
        }
    }
    __syncthreads();
    #pragma unroll
    for (int i=0;i<16;i++) S[(rg*16+i)*64 + k] = acc[i];
    __syncthreads();
    #pragma unroll
    for (int i=0;i<16;i++) acc[i]=make_float2(0.f,0.f);
    for (int r=0;r<64;r++) {
        float2 bv = S[r*64 + k];
        #pragma unroll
        for (int i=0;i<16;i++) {
            float2 d = g_D64f[r*64 + rg*16 + i];
            acc[i].x = fmaf(bv.x, d.x, fmaf(-bv.y, d.y, acc[i].x));
            acc[i].y = fmaf(bv.x, d.y, fmaf( bv.y, d.x, acc[i].y));
        }
    }
    float2* dst = g_f + (size_t)img*4096;
    #pragma unroll
    for (int i=0;i<16;i++) dst[(rg*16+i)*64 + k] = acc[i];
}

// ---------------- inverse row norms ----------------
__global__ void k_invnorm() {
    int row = blockIdx.x;
    const float2* p = g_f + (size_t)row*4096;
    float s = 0.f;
    for (int i=threadIdx.x;i<4096;i+=256) { float2 v = p[i]; s = fmaf(v.x,v.x,fmaf(v.y,v.y,s)); }
    __shared__ float red[256];
    red[threadIdx.x]=s; __syncthreads();
    for (int st=128;st>0;st>>=1){ if(threadIdx.x<st) red[threadIdx.x]+=red[threadIdx.x+st]; __syncthreads(); }
    if (threadIdx.x==0) g_invn[row] = 1.f / fmaxf(sqrtf(red[0]), 1e-12f);
}

// ---------------- attention logit partials ----------------
__global__ void k_attn() {
    __shared__ float2 F[32*65];
    int bh = blockIdx.x, p = blockIdx.y;
    int b = bh >> 3, hd = bh & 7;
    int t = threadIdx.x;
    int d = t & 31, cg = t >> 5;
    float2 acc[4];
    #pragma unroll
    for (int i=0;i<4;i++) acc[i]=make_float2(0.f,0.f);
    const float2* base = g_f + (((size_t)b*256 + hd*32)*4096);
    for (int n0 = p*1024; n0 < p*1024+1024; n0 += 64) {
        __syncthreads();
        for (int e=t; e<2048; e+=256) {
            int cc = e >> 6, j = e & 63;
            F[cc*65+j] = base[(size_t)cc*4096 + n0 + j];
        }
        __syncthreads();
        for (int j=0;j<64;j++) {
            float2 vd = F[d*65+j];
            #pragma unroll
            for (int i=0;i<4;i++) {
                float2 vc = F[(cg*4+i)*65 + j];
                acc[i].x = fmaf(vc.x,vd.x, fmaf(-vc.y,vd.y, acc[i].x));
                acc[i].y = fmaf(vc.x,vd.y, fmaf( vc.y,vd.x, acc[i].y));
            }
        }
    }
    float2* dst = g_attnp + ((size_t)p*64 + bh)*1024;
    #pragma unroll
    for (int i=0;i<4;i++) dst[(cg*4+i)*32 + d] = acc[i];
}

// ---------------- reduce partials + scale + softmax(re/im) ----------------
__global__ void k_softmax(const float* __restrict__ temperature) {
    int w = threadIdx.x >> 5, lane = threadIdx.x & 31;
    int row = blockIdx.x*8 + w;
    int b = row >> 8, ch = row & 255; int hd = ch >> 5, c = ch & 31;
    int bh = b*8+hd;
    size_t idx = (size_t)bh*1024 + c*32 + lane;
    float2 v = make_float2(0.f,0.f);
    for (int p=0;p<4;p++){ float2 q = g_attnp[(size_t)p*65536 + idx]; v.x+=q.x; v.y+=q.y; }
    float scale = g_invn[row] * g_invn[b*256 + hd*32 + lane] * temperature[hd];
    float re = v.x*scale, im = v.y*scale;
    float mre = re, mim = im;
    for (int s=16;s>0;s>>=1){ mre = fmaxf(mre, __shfl_xor_sync(0xffffffffu, mre, s));
                              mim = fmaxf(mim, __shfl_xor_sync(0xffffffffu, mim, s)); }
    float ere = expf(re-mre), eim = expf(im-mim);
    float sre=ere, sim=eim;
    for (int s=16;s>0;s>>=1){ sre += __shfl_xor_sync(0xffffffffu,sre,s);
                              sim += __shfl_xor_sync(0xffffffffu,sim,s); }
    g_attn[idx] = make_float2(ere/sre, eim/sim);
}

// ---------------- apply attention ----------------
__global__ void k_apply() {
    __shared__ float2 As[1024];
    int bh = blockIdx.x, nc = blockIdx.y;
    int b = bh>>3, hd = bh&7;
    int t = threadIdx.x;
    for (int e=t;e<1024;e+=256) As[e] = g_attn[(size_t)bh*1024 + e];
    __syncthreads();
    int n = nc*256 + t;
    const float2* fb = g_f + ((size_t)b*256 + hd*32)*4096 + n;
    float2 acc[32];
    #pragma unroll
    for (int c=0;c<32;c++) acc[c]=make_float2(0.f,0.f);
    for (int d=0;d<32;d++) {
        float2 v = fb[(size_t)d*4096];
        #pragma unroll
        for (int c=0;c<32;c++) {
            float2 a = As[c*32+d];
            acc[c].x = fmaf(a.x,v.x, fmaf(-a.y,v.y, acc[c].x));
            acc[c].y = fmaf(a.x,v.y, fmaf( a.y,v.x, acc[c].y));
        }
    }
    float2* ob = g_t + ((size_t)b*256 + hd*32)*4096 + n;
    #pragma unroll
    for (int c=0;c<32;c++) ob[(size_t)c*4096] = acc[c];
}

// ---------------- ifft over length-32 channel axis ----------------
__global__ void k_ifft32() {
    __shared__ float2 D[1024];
    int bh = blockIdx.x, nc = blockIdx.y;
    int t = threadIdx.x;
    for (int e=t;e<1024;e+=256) D[e] = g_D32i[e];
    __syncthreads();
    int b = bh>>3, hd = bh&7;
    int n = nc*256 + t;
    float2* col = g_t + ((size_t)b*256+hd*32)*4096 + n;
    float2 acc[32];
    #pragma unroll
    for (int k=0;k<32;k++) acc[k]=make_float2(0.f,0.f);
    for (int c=0;c<32;c++) {
        float2 v = col[(size_t)c*4096];
        #pragma unroll
        for (int k=0;k<32;k++) {
            float2 d = D[c*32+k];
            acc[k].x = fmaf(v.x,d.x, fmaf(-v.y,d.y,acc[k].x));
            acc[k].y = fmaf(v.x,d.y, fmaf( v.y,d.x,acc[k].y));
        }
    }
    #pragma unroll
    for (int k=0;k<32;k++) col[(size_t)k*4096] = acc[k];
}

// ---------------- ifft-4096 per row ----------------
__global__ void k_ifft4096() {
    __shared__ float2 S[4224];
    int row = blockIdx.x;
    int t = threadIdx.x;
    const float2* src = g_t + (size_t)row*4096;
    for (int i=t;i<4096;i+=256) S[i]=src[i];
    __syncthreads();
    int k = t&63, rg = t>>6;
    float2 acc[16];
    #pragma unroll
    for(int i=0;i<16;i++)acc[i]=make_float2(0.f,0.f);
    for (int n1=0;n1<64;n1++){
        float2 a = S[n1*64 + k];
        #pragma unroll
        for (int i=0;i<16;i++){
            float2 d = g_D64i[n1*64 + rg*16+i];
            acc[i].x = fmaf(a.x,d.x,fmaf(-a.y,d.y,acc[i].x));
            acc[i].y = fmaf(a.x,d.y,fmaf( a.y,d.x,acc[i].y));
        }
    }
    __syncthreads();
    #pragma unroll
    for (int i=0;i<16;i++){
        int k1 = rg*16+i;
        float2 tw = g_tw[k*64 + k1];
        float2 v; v.x = acc[i].x*tw.x - acc[i].y*tw.y; v.y = acc[i].x*tw.y + acc[i].y*tw.x;
        S[k1*64 + k] = v;
    }
    __syncthreads();
    #pragma unroll
    for(int i=0;i<16;i++)acc[i]=make_float2(0.f,0.f);
    for (int n2=0;n2<64;n2++){
        float2 d = g_D64i[n2*64 + k];
        #pragma unroll
        for (int i=0;i<16;i++){
            float2 bv = S[(rg*16+i)*64 + n2];
            acc[i].x = fmaf(bv.x,d.x,fmaf(-bv.y,d.y,acc[i].x));
            acc[i].y = fmaf(bv.x,d.y,fmaf( bv.y,d.x,acc[i].y));
        }
    }
    __syncthreads();
    #pragma unroll
    for (int i=0;i<16;i++) S[k*66 + rg*16+i] = acc[i];
    __syncthreads();
    int b = row >> 8, ch = row & 255;
    float* dst = g_out2 + ((size_t)b*512 + ch)*4096;
    const float inv = 1.f/4096.f;
    for (int i=t;i<4096;i+=256){ float2 v=S[(i>>6)*66 + (i&63)]; dst[i] = sqrtf(v.x*v.x+v.y*v.y)*inv; }
}

// ---------------- gating MLP + gate*f -> g_t ----------------
__global__ void k_gate(const float* __restrict__ w1_w, const float* __restrict__ w1_b,
                       const float* __restrict__ bnw_g, const float* __restrict__ bnw_b,
                       const float* __restrict__ bnw_m, const float* __restrict__ bnw_v,
                       const float* __restrict__ w2_w, const float* __restrict__ w2_b) {
    __shared__ float w1s[16*256];
    __shared__ float w2s[256*16];
    __shared__ float aw[16], dw[16], b2s[256];
    int b = blockIdx.x, nc = blockIdx.y;
    int t = threadIdx.x;
    for (int e=t;e<4096;e+=256){ w1s[e]=w1_w[e]; w2s[e]=w2_w[e]; }
    if (t<16){ float a = bnw_g[t]*rsqrtf(bnw_v[t]+1e-5f); aw[t]=a; dw[t]=(w1_b[t]-bnw_m[t])*a + bnw_b[t]; }
    b2s[t]=w2_b[t];
    __syncthreads();
    int n = nc*256 + t;
    const float2* fb = g_f + (size_t)b*256*4096 + n;
    float g1[16];
    #pragma unroll
    for (int j=0;j<16;j++) g1[j]=0.f;
    for (int c=0;c<256;c++){
        float v = fb[(size_t)c*4096].x;
        #pragma unroll
        for (int j=0;j<16;j++) g1[j] = fmaf(w1s[j*256+c], v, g1[j]);
    }
    #pragma unroll
    for (int j=0;j<16;j++) g1[j] = fmaxf(fmaf(g1[j], aw[j], dw[j]), 0.f);
    float2* ob = g_t + (size_t)b*256*4096 + n;
    for (int c=0;c<256;c++){
        float s = b2s[c];
        #pragma unroll
        for (int j=0;j<16;j++) s = fmaf(w2s[c*16+j], g1[j], s);
        float gt = 1.f/(1.f + expf(-s));
        float2 fv = fb[(size_t)c*4096];
        ob[(size_t)c*4096] = make_float2(fv.x*gt, fv.y*gt);
    }
}

// ---------------- ifft2 64x64 of gate*f ----------------
__global__ void k_ifft2_gate() {
    __shared__ float2 S[4096];
    int img = blockIdx.x;
    int t = threadIdx.x;
    const float2* src = g_t + (size_t)img*4096;
    for (int i=t;i<4096;i+=256) S[i]=src[i];
    __syncthreads();
    int k=t&63, rg=t>>6;
    float2 acc[16];
    #pragma unroll
    for(int i=0;i<16;i++)acc[i]=make_float2(0.f,0.f);
    for (int n=0;n<64;n++){
        float2 d = g_D64i[n*64+k];
        #pragma unroll
        for (int i=0;i<16;i++){
            float2 a = S[(rg*16+i)*64+n];
            acc[i].x = fmaf(a.x,d.x,fmaf(-a.y,d.y,acc[i].x));
            acc[i].y = fmaf(a.x,d.y,fmaf( a.y,d.x,acc[i].y));
        }
    }
    __syncthreads();
    #pragma unroll
    for (int i=0;i<16;i++) S[(rg*16+i)*64+k]=acc[i];
    __syncthreads();
    #pragma unroll
    for(int i=0;i<16;i++)acc[i]=make_float2(0.f,0.f);
    for (int r=0;r<64;r++){
        float2 bv = S[r*64+k];
        #pragma unroll
        for (int i=0;i<16;i++){
            float2 d = g_D64i[r*64+rg*16+i];
            acc[i].x = fmaf(bv.x,d.x,fmaf(-bv.y,d.y,acc[i].x));
            acc[i].y = fmaf(bv.x,d.y,fmaf( bv.y,d.x,acc[i].y));
        }
    }
    int b = img>>8, ch = img&255;
    float* dst = g_out2 + ((size_t)b*512 + 256 + ch)*4096;
    const float inv = 1.f/4096.f;
    #pragma unroll
    for (int i=0;i<16;i++){
        float2 v = acc[i];
        dst[(rg*16+i)*64 + k] = sqrtf(v.x*v.x+v.y*v.y)*inv;
    }
}

// ---------------- residual add + bf16 split transpose -> [n][ch] ----------------
__global__ void k_addx(const float* __restrict__ x) {
    __shared__ float s[32][33];
    int b = blockIdx.z;
    int ch0 = blockIdx.y*32;
    int n0 = blockIdx.x*32;
    int tj = threadIdx.x & 31;
    int ti = threadIdx.x >> 5;
    for (int i=ti;i<32;i+=8)
        s[i][tj] = g_out2[((size_t)b*512 + ch0+i)*4096 + n0 + tj];
    __syncthreads();
    for (int j=ti;j<32;j+=8) {
        int n = n0 + j, ch = ch0 + tj;
        size_t oidx = ((size_t)b*4096 + n)*512 + ch;
        float v = s[tj][j] + x[oidx];
        __nv_bfloat16 h = __float2bfloat16(v);
        g_o2hi[oidx] = h;
        g_o2lo[oidx] = __float2bfloat16(v - __bfloat162float(h));
    }
}

// ---------------- projection GEMM via HMMA (bf16 split, 3-stage) ----------------
__global__ void __launch_bounds__(256, 1) k_proj_hmma(const float* __restrict__ pb,
                                                      float* __restrict__ out) {
    extern __shared__ char smem[];
    uint32_t sb = smem_u32(smem);
    int tid = threadIdx.x, wid = tid >> 5, lane = tid & 31;
    int b = blockIdx.z;
    int m0 = blockIdx.x << 7;          // n tile (128 rows)
    int nt0 = blockIdx.y << 8;         // o tile (256 cols)
    int wm = wid & 1, wn = wid >> 1;

    float c[4][8][4];
    #pragma unroll
    for (int i = 0; i < 4; i++)
        #pragma unroll
        for (int j = 0; j < 8; j++)
            #pragma unroll
            for (int r = 0; r < 4; r++) c[i][j][r] = 0.f;

    auto issue = [&](int chunk) {
        int pass = chunk >> 3, c0 = (chunk & 7) << 6;
        const __nv_bfloat16* as = ((pass == 2) ? g_o2lo : g_o2hi) + ((size_t)b*4096 + m0)*512 + c0;
        const __nv_bfloat16* ws = ((pass == 1) ? g_pwlo : g_pwhi) + (size_t)nt0*512 + c0;
        uint32_t bo = (uint32_t)(chunk % CONV_STAGES) * CH_BYTES;
        #pragma unroll
        for (int i = 0; i < 4; i++) {
            int idx = tid + i*256;
            int r = idx >> 3, q = idx & 7;
            cp_async16(sb + bo + swz128((uint32_t)(r*128 + q*16)), as + (size_t)r*512 + q*8, 16);
        }
        #pragma unroll
        for (int i = 0; i < 8; i++) {
            int idx = tid + i*256;
            int o = idx >> 3, q = idx & 7;
            cp_async16(sb + bo + 16384u + swz128((uint32_t)(o*128 + q*16)),
                       ws + (size_t)o*512 + q*8, 16);
        }
        asm volatile("cp.async.commit_group;" ::: "memory");
    };

    issue(0); issue(1);
    int sub = lane >> 3, lr = lane & 7;
    #pragma unroll 1
    for (int ch = 0; ch < 24; ch++) {
        if (ch + 2 < 24) {
            issue(ch + 2);
            asm volatile("cp.async.wait_group 2;" ::: "memory");
        } else {
            asm volatile("cp.async.wait_group 0;" ::: "memory");
        }
        __syncthreads();
        uint32_t aBase = sb + (uint32_t)(ch % CONV_STAGES) * CH_BYTES;
        uint32_t bBase = aBase + 16384u;
        #pragma unroll
        for (int k16 = 0; k16 < 4; k16++) {
            uint32_t kb = (uint32_t)(k16*32);
            uint32_t a[4][4];
            #pragma unroll
            for (int mf = 0; mf < 4; mf++) {
                uint32_t row = (uint32_t)(wm*64 + mf*16 + ((sub & 1) << 3) + lr);
                uint32_t col = kb + ((uint32_t)(sub >> 1) << 4);
                ldmx4(a[mf], aBase + swz128(row*128 + col));
            }
            #pragma unroll
            for (int nfp = 0; nfp < 4; nfp++) {
                uint32_t brow = (uint32_t)(wn*64 + nfp*16 + ((sub & 2) << 2) + lr);
                uint32_t bcol = kb + ((uint32_t)(sub & 1) << 4);
                uint32_t bf[4];
                ldmx4(bf, bBase + swz128(brow*128 + bcol));
                #pragma unroll
                for (int mf = 0; mf < 4; mf++) {
                    mma16816(c[mf][nfp*2],     a[mf], bf[0], bf[1]);
                    mma16816(c[mf][nfp*2 + 1], a[mf], bf[2], bf[3]);
                }
            }
        }
        __syncthreads();
    }

    #pragma unroll
    for (int nf = 0; nf < 8; nf++) {
        int o = nt0 + wn*64 + nf*8 + (lane & 3)*2;
        float p0 = pb[o], p1 = pb[o+1];
        #pragma unroll
        for (int mf = 0; mf < 4; mf++) {
            int n = m0 + wm*64 + mf*16 + (lane >> 2);
            float* d = out + ((size_t)b*4096 + n)*512 + o;
            d[0]   = c[mf][nf][0] + p0;
            d[1]   = c[mf][nf][1] + p1;
            d += 8*512;
            d[0]   = c[mf][nf][2] + p0;
            d[1]   = c[mf][nf][3] + p1;
        }
    }
}

// ---------------- launch ----------------
extern "C" void kernel_launch(void* const* d_in, const int* in_sizes, int n_in,
                              void* d_out, int out_size) {
    const float* x        = (const float*)d_in[0];
    const float* conv2_w  = (const float*)d_in[1];
    const float* conv2_b  = (const float*)d_in[2];
    const float* bn2_g    = (const float*)d_in[3];
    const float* bn2_b    = (const float*)d_in[4];
    const float* bn2_m    = (const float*)d_in[5];
    const float* bn2_v    = (const float*)d_in[6];
    const float* temp     = (const float*)d_in[7];
    const float* w1_w     = (const float*)d_in[8];
    const float* w1_b     = (const float*)d_in[9];
    const float* bnw_g    = (const float*)d_in[10];
    const float* bnw_b    = (const float*)d_in[11];
    const float* bnw_m    = (const float*)d_in[12];
    const float* bnw_v    = (const float*)d_in[13];
    const float* w2_w     = (const float*)d_in[14];
    const float* w2_b     = (const float*)d_in[15];
    const float* proj_w   = (const float*)d_in[16];
    const float* proj_b   = (const float*)d_in[17];
    float* out = (float*)d_out;

    static bool attr_set = false;
    if (!attr_set) {
        cudaFuncSetAttribute(k_conv_hmma, cudaFuncAttributeMaxDynamicSharedMemorySize, CONV_SMEM);
        cudaFuncSetAttribute(k_proj_hmma, cudaFuncAttributeMaxDynamicSharedMemorySize, CONV_SMEM);
        attr_set = true;
    }

    k_split_x<<<65536,256>>>(x);
    k_split_w<<<4608,256>>>(conv2_w);
    k_split_pw<<<1024,256>>>(proj_w);
    k_prep_misc<<<1024,256>>>(conv2_b, bn2_g, bn2_b, bn2_m, bn2_v);
    k_conv_hmma<<<256,256,CONV_SMEM>>>();
    k_fft2_fwd<<<2048,256>>>();
    k_invnorm<<<2048,256>>>();
    k_attn<<<dim3(64,4),256>>>();
    k_softmax<<<256,256>>>(temp);
    k_apply<<<dim3(64,16),256>>>();
    k_ifft32<<<dim3(64,16),256>>>();
    k_ifft4096<<<2048,256>>>();
    k_gate<<<dim3(8,16),256>>>(w1_w,w1_b,bnw_g,bnw_b,bnw_m,bnw_v,w2_w,w2_b);
    k_ifft2_gate<<<2048,256>>>();
    k_addx<<<dim3(128,16,8),256>>>(x);
    k_proj_hmma<<<dim3(32,2,8),256,CONV_SMEM>>>(proj_b, out);
}